// round 2
// baseline (speedup 1.0000x reference)
#include <cuda_runtime.h>
#include <float.h>

#define BB 4
#define SS 2048
#define HH 1024

// Scratch (allocation-free: __device__ globals)
__device__ float g_q[(size_t)BB * SS * HH];
__device__ float g_k[(size_t)BB * SS * HH];
__device__ float g_v[(size_t)BB * SS * HH];
__device__ float g_po[(size_t)BB * SS * HH];
__device__ float g_attn[(size_t)BB * SS * SS];

// ---------------------------------------------------------------------------
// Tiled SGEMM: C[M,N] = A[M,K] @ op(B) (+ bias[N])
//   TRANSB=true : op(B) = B^T where B is [N,K] row-major  (x @ W.T, Q @ K^T)
//   TRANSB=false: op(B) = B   where B is [K,N] row-major  (attn @ V)
// Batched over blockIdx.z with element strides sA/sB/sC.
// Requires M%128==0, N%128==0, K%8==0 (true for all shapes here).
// BM=BN=128, BK=8, 256 threads, 8x8 per-thread microtile.
// ---------------------------------------------------------------------------
template <bool TRANSB, bool HASBIAS>
__global__ __launch_bounds__(256) void sgemm_kernel(
    const float* __restrict__ A, const float* __restrict__ B,
    const float* __restrict__ bias, float* __restrict__ C,
    int M, int N, int K,
    long long sA, long long sB, long long sC)
{
    constexpr int BM = 128, BN = 128, BK = 8;
    __shared__ float As[BK][BM];
    __shared__ float Bs[BK][BN];

    const int tid = threadIdx.x;
    const int m0 = blockIdx.y * BM;
    const int n0 = blockIdx.x * BN;

    A += (long long)blockIdx.z * sA;
    B += (long long)blockIdx.z * sB;
    C += (long long)blockIdx.z * sC;

    // A-tile loader mapping (also used for B when TRANSB): 128 rows x 8 k
    const int ar = tid >> 1;          // 0..127 row-in-tile
    const int ac = (tid & 1) * 4;     // 0 or 4  k-in-tile
    // B-tile loader mapping for NN: 8 k-rows x 128 n
    const int br = tid >> 5;          // 0..7
    const int bc = (tid & 31) * 4;    // 0..124

    // Compute mapping
    const int ty = tid >> 4;          // 0..15 -> rows m0 + ty*8 ..
    const int tx = tid & 15;          // 0..15 -> cols n0 + tx*8 ..

    float acc[8][8];
#pragma unroll
    for (int i = 0; i < 8; i++)
#pragma unroll
        for (int j = 0; j < 8; j++) acc[i][j] = 0.0f;

    for (int k0 = 0; k0 < K; k0 += BK) {
        // Load A tile (transposed into smem: As[k][m])
        float4 a4 = *reinterpret_cast<const float4*>(
            A + (long long)(m0 + ar) * K + (k0 + ac));
        As[ac + 0][ar] = a4.x;
        As[ac + 1][ar] = a4.y;
        As[ac + 2][ar] = a4.z;
        As[ac + 3][ar] = a4.w;

        if (TRANSB) {
            // B is [N,K]; Bs[k][n] = B[n0+n][k0+k]
            float4 b4 = *reinterpret_cast<const float4*>(
                B + (long long)(n0 + ar) * K + (k0 + ac));
            Bs[ac + 0][ar] = b4.x;
            Bs[ac + 1][ar] = b4.y;
            Bs[ac + 2][ar] = b4.z;
            Bs[ac + 3][ar] = b4.w;
        } else {
            // B is [K,N]; Bs[k][n] = B[k0+k][n0+n]
            float4 b4 = *reinterpret_cast<const float4*>(
                B + (long long)(k0 + br) * N + (n0 + bc));
            *reinterpret_cast<float4*>(&Bs[br][bc]) = b4;
        }
        __syncthreads();

#pragma unroll
        for (int kk = 0; kk < BK; kk++) {
            float af[8], bf[8];
#pragma unroll
            for (int i = 0; i < 8; i++) af[i] = As[kk][ty * 8 + i];
#pragma unroll
            for (int j = 0; j < 8; j++) bf[j] = Bs[kk][tx * 8 + j];
#pragma unroll
            for (int i = 0; i < 8; i++)
#pragma unroll
                for (int j = 0; j < 8; j++) acc[i][j] = fmaf(af[i], bf[j], acc[i][j]);
        }
        __syncthreads();
    }

    // Epilogue
    float bv[8];
#pragma unroll
    for (int j = 0; j < 8; j++)
        bv[j] = HASBIAS ? bias[n0 + tx * 8 + j] : 0.0f;

#pragma unroll
    for (int i = 0; i < 8; i++) {
        long long roff = (long long)(m0 + ty * 8 + i) * N + n0 + tx * 8;
#pragma unroll
        for (int j = 0; j < 8; j++)
            C[roff + j] = acc[i][j] + bv[j];
    }
}

// ---------------------------------------------------------------------------
// Row softmax over attn[b][i][:] with scale, causal mask (j<=i), key mask.
// One block (256 threads) per row. Matches reference: masked -> finfo.min
// sentinel (we use -FLT_MAX), softmax in fp32; all-masked row -> uniform.
// ---------------------------------------------------------------------------
__global__ __launch_bounds__(256) void softmax_kernel(
    float* __restrict__ attn, const int* __restrict__ mask)
{
    const int row = blockIdx.x;
    const int b = row / SS;
    const int i = row % SS;
    float* p = attn + (size_t)b * SS * SS + (size_t)i * SS;
    const int* mrow = mask + (size_t)b * SS;
    const float scale = 0.03125f;  // 1024^-0.5

    __shared__ float red[256];
    const int tid = threadIdx.x;

    // Pass 1: max
    float mx = -FLT_MAX;
    for (int j = tid; j < SS; j += 256) {
        float v = (j <= i && mrow[j] != 0) ? p[j] * scale : -FLT_MAX;
        mx = fmaxf(mx, v);
    }
    red[tid] = mx;
    __syncthreads();
    for (int s = 128; s > 0; s >>= 1) {
        if (tid < s) red[tid] = fmaxf(red[tid], red[tid + s]);
        __syncthreads();
    }
    mx = red[0];
    __syncthreads();

    // Pass 2: exp + sum (write exp back)
    float sum = 0.0f;
    for (int j = tid; j < SS; j += 256) {
        float v = (j <= i && mrow[j] != 0) ? p[j] * scale : -FLT_MAX;
        float e = __expf(v - mx);   // -FLT_MAX - mx -> huge negative -> 0
        p[j] = e;
        sum += e;
    }
    red[tid] = sum;
    __syncthreads();
    for (int s = 128; s > 0; s >>= 1) {
        if (tid < s) red[tid] += red[tid + s];
        __syncthreads();
    }
    const float inv = 1.0f / red[0];

    // Pass 3: normalize
    for (int j = tid; j < SS; j += 256) p[j] *= inv;
}

extern "C" void kernel_launch(void* const* d_in, const int* in_sizes, int n_in,
                              void* d_out, int out_size)
{
    const float* x    = (const float*)d_in[0];
    const int*   mask = (const int*)  d_in[1];
    const float* Wq   = (const float*)d_in[2];
    const float* bq   = (const float*)d_in[3];
    const float* Wk   = (const float*)d_in[4];
    const float* bk   = (const float*)d_in[5];
    const float* Wv   = (const float*)d_in[6];
    const float* bv   = (const float*)d_in[7];
    const float* Wo   = (const float*)d_in[8];
    const float* bo   = (const float*)d_in[9];

    float* q;  cudaGetSymbolAddress((void**)&q,  g_q);
    float* k;  cudaGetSymbolAddress((void**)&k,  g_k);
    float* v;  cudaGetSymbolAddress((void**)&v,  g_v);
    float* po; cudaGetSymbolAddress((void**)&po, g_po);
    float* attn_scratch; cudaGetSymbolAddress((void**)&attn_scratch, g_attn);

    const long long OUT_N  = (long long)BB * SS * HH;  //  8388608
    const long long ATTN_N = (long long)BB * SS * SS;  // 16777216

    float* out_dst  = (float*)d_out;
    float* attn_dst = attn_scratch;
    if ((long long)out_size >= OUT_N + ATTN_N) {
        // harness expects (out, attn) concatenated
        attn_dst = (float*)d_out + OUT_N;
    } else if ((long long)out_size == ATTN_N) {
        // attn only
        attn_dst = (float*)d_out;
        out_dst  = q;  // q is dead after scores; safe dump for unused out
    }

    const int M_TOK = BB * SS;  // 8192

    // 1) QKV projections: [8192,1024] @ W^T + b
    {
        dim3 grid(HH / 128, M_TOK / 128, 1), blk(256);
        sgemm_kernel<true, true><<<grid, blk>>>(x, Wq, bq, q, M_TOK, HH, HH, 0, 0, 0);
        sgemm_kernel<true, true><<<grid, blk>>>(x, Wk, bk, k, M_TOK, HH, HH, 0, 0, 0);
        sgemm_kernel<true, true><<<grid, blk>>>(x, Wv, bv, v, M_TOK, HH, HH, 0, 0, 0);
    }

    // 2) scores = Q @ K^T per batch -> attn_dst (raw, pre-scale)
    {
        dim3 grid(SS / 128, SS / 128, BB), blk(256);
        sgemm_kernel<true, false><<<grid, blk>>>(
            q, k, nullptr, attn_dst, SS, SS, HH,
            (long long)SS * HH, (long long)SS * HH, (long long)SS * SS);
    }

    // 3) softmax rows (scale + causal + key mask)
    softmax_kernel<<<BB * SS, 256>>>(attn_dst, mask);

    // 4) PV: attn @ V per batch -> po
    {
        dim3 grid(HH / 128, SS / 128, BB), blk(256);
        sgemm_kernel<false, false><<<grid, blk>>>(
            attn_dst, v, nullptr, po, SS, HH, SS,
            (long long)SS * SS, (long long)SS * HH, (long long)SS * HH);
    }

    // 5) output projection: po @ Wo^T + bo -> out
    {
        dim3 grid(HH / 128, M_TOK / 128, 1), blk(256);
        sgemm_kernel<true, true><<<grid, blk>>>(po, Wo, bo, out_dst, M_TOK, HH, HH, 0, 0, 0);
    }
}

// round 4
// speedup vs baseline: 3.6226x; 3.6226x over previous
#include <cuda_runtime.h>
#include <cstdint>
#include <float.h>

#define BB 4
#define SS 2048
#define HH 1024

// ---------------- scratch (allocation-free) ----------------
__device__ float g_q [(size_t)BB * SS * HH];
__device__ float g_k [(size_t)BB * SS * HH];
__device__ float g_v [(size_t)BB * SS * HH];
__device__ float g_vt[(size_t)BB * SS * HH];
__device__ float g_po[(size_t)BB * SS * HH];
__device__ float g_attn[(size_t)BB * SS * SS];

__device__ __forceinline__ uint32_t smem_u32(const void* p) {
    uint32_t a;
    asm("{ .reg .u64 t; cvta.to.shared.u64 t, %1; cvt.u32.u64 %0, t; }" : "=r"(a) : "l"(p));
    return a;
}
__device__ __forceinline__ uint32_t f2tf32(float f) {
    uint32_t r;
    asm("cvt.rna.tf32.f32 %0, %1;" : "=r"(r) : "f"(f));
    return r;
}
__device__ __forceinline__ void cp_async16(uint32_t saddr, const void* gptr) {
    asm volatile("cp.async.cg.shared.global [%0], [%1], 16;"
                 :: "r"(saddr), "l"(gptr) : "memory");
}
#define CP_COMMIT() asm volatile("cp.async.commit_group;" ::: "memory")

__device__ __forceinline__ void mma_tf32(float& c0, float& c1, float& c2, float& c3,
                                         uint32_t a0, uint32_t a1, uint32_t a2, uint32_t a3,
                                         uint32_t b0, uint32_t b1) {
    asm volatile(
        "mma.sync.aligned.m16n8k8.row.col.f32.tf32.tf32.f32 "
        "{%0,%1,%2,%3}, {%4,%5,%6,%7}, {%8,%9}, {%0,%1,%2,%3};"
        : "+f"(c0), "+f"(c1), "+f"(c2), "+f"(c3)
        : "r"(a0), "r"(a1), "r"(a2), "r"(a3), "r"(b0), "r"(b1));
}

// ---------------------------------------------------------------------------
// NT tf32 tensor-core GEMM: C[M,N] = A[M,K] @ B^T (+bias)
//   A: [M,K] row-major, B: [N,K] row-major. Batched via blockIdx.z.
// Tile 128x128x16, 256 threads (8 warps, 2x4), warp tile 64x32,
// m16n8k8 MMAs, cp.async double buffer, padded smem (stride 20 floats:
// fragment LDS banks (20g+tig)%32 all-distinct -> conflict-free).
// Requires M%128==0, N%128==0, K%16==0.
// ---------------------------------------------------------------------------
#define LDSF 20  // floats per smem row (16 + 4 pad); 80B, keeps 16B alignment

template <bool HASBIAS>
__global__ __launch_bounds__(256) void mma_gemm_nt(
    const float* __restrict__ A, const float* __restrict__ B,
    const float* __restrict__ bias, float* __restrict__ C,
    int M, int N, int K,
    long long strA, long long strB, long long strC)
{
    __shared__ float As[2][128 * LDSF];
    __shared__ float Bs[2][128 * LDSF];

    const int tid  = threadIdx.x;
    const int wid  = tid >> 5;
    const int lane = tid & 31;
    const int g    = lane >> 2;   // groupID 0..7
    const int tig  = lane & 3;    // thread-in-group 0..3
    const int m0   = blockIdx.y * 128;
    const int n0   = blockIdx.x * 128;
    const int wm   = (wid >> 2) * 64;  // warp m offset (0 or 64)
    const int wn   = (wid & 3) * 32;   // warp n offset

    A += (long long)blockIdx.z * strA;
    B += (long long)blockIdx.z * strB;
    C += (long long)blockIdx.z * strC;

    const uint32_t sAs = smem_u32(&As[0][0]);
    const uint32_t sBs = smem_u32(&Bs[0][0]);
    // loader mapping: idx in [0,512): row = idx>>2, 16B chunk = idx&3
    const int lrow0 = tid >> 2;            // idx = tid
    const int lch0  = tid & 3;
    const int lrow1 = (tid + 256) >> 2;    // idx = tid + 256
    const int lch1  = lch0;                // (tid+256)&3 == tid&3

    float acc[4][4][4];
#pragma unroll
    for (int i = 0; i < 4; i++)
#pragma unroll
        for (int j = 0; j < 4; j++)
#pragma unroll
            for (int r = 0; r < 4; r++) acc[i][j][r] = 0.0f;

    const int T = K >> 4;

    // ---- prefetch tile 0 ----
    {
        const int k0 = 0;
        cp_async16(sAs + (uint32_t)(lrow0 * LDSF + lch0 * 4) * 4,
                   A + (size_t)(m0 + lrow0) * K + k0 + lch0 * 4);
        cp_async16(sAs + (uint32_t)(lrow1 * LDSF + lch1 * 4) * 4,
                   A + (size_t)(m0 + lrow1) * K + k0 + lch1 * 4);
        cp_async16(sBs + (uint32_t)(lrow0 * LDSF + lch0 * 4) * 4,
                   B + (size_t)(n0 + lrow0) * K + k0 + lch0 * 4);
        cp_async16(sBs + (uint32_t)(lrow1 * LDSF + lch1 * 4) * 4,
                   B + (size_t)(n0 + lrow1) * K + k0 + lch1 * 4);
        CP_COMMIT();
    }

    for (int t = 0; t < T; t++) {
        const int buf = t & 1;
        if (t + 1 < T) {
            const int nb = (t + 1) & 1;
            const int k0 = (t + 1) << 4;
            const uint32_t sa = sAs + (uint32_t)nb * (128 * LDSF * 4);
            const uint32_t sb = sBs + (uint32_t)nb * (128 * LDSF * 4);
            cp_async16(sa + (uint32_t)(lrow0 * LDSF + lch0 * 4) * 4,
                       A + (size_t)(m0 + lrow0) * K + k0 + lch0 * 4);
            cp_async16(sa + (uint32_t)(lrow1 * LDSF + lch1 * 4) * 4,
                       A + (size_t)(m0 + lrow1) * K + k0 + lch1 * 4);
            cp_async16(sb + (uint32_t)(lrow0 * LDSF + lch0 * 4) * 4,
                       B + (size_t)(n0 + lrow0) * K + k0 + lch0 * 4);
            cp_async16(sb + (uint32_t)(lrow1 * LDSF + lch1 * 4) * 4,
                       B + (size_t)(n0 + lrow1) * K + k0 + lch1 * 4);
            CP_COMMIT();
            asm volatile("cp.async.wait_group 1;" ::: "memory");
        } else {
            asm volatile("cp.async.wait_group 0;" ::: "memory");
        }
        __syncthreads();

        const float* Ab = As[buf];
        const float* Bb = Bs[buf];
#pragma unroll
        for (int kk = 0; kk < 16; kk += 8) {
            uint32_t af[4][4], bf[4][2];
#pragma unroll
            for (int i = 0; i < 4; i++) {
                const int mr = wm + i * 16 + g;
                af[i][0] = f2tf32(Ab[mr * LDSF + kk + tig]);
                af[i][1] = f2tf32(Ab[(mr + 8) * LDSF + kk + tig]);
                af[i][2] = f2tf32(Ab[mr * LDSF + kk + tig + 4]);
                af[i][3] = f2tf32(Ab[(mr + 8) * LDSF + kk + tig + 4]);
            }
#pragma unroll
            for (int j = 0; j < 4; j++) {
                const int nr = wn + j * 8 + g;
                bf[j][0] = f2tf32(Bb[nr * LDSF + kk + tig]);
                bf[j][1] = f2tf32(Bb[nr * LDSF + kk + tig + 4]);
            }
#pragma unroll
            for (int i = 0; i < 4; i++)
#pragma unroll
                for (int j = 0; j < 4; j++)
                    mma_tf32(acc[i][j][0], acc[i][j][1], acc[i][j][2], acc[i][j][3],
                             af[i][0], af[i][1], af[i][2], af[i][3],
                             bf[j][0], bf[j][1]);
        }
        __syncthreads();
    }

    // ---- epilogue ----
#pragma unroll
    for (int i = 0; i < 4; i++) {
        const int r0 = m0 + wm + i * 16 + g;
#pragma unroll
        for (int j = 0; j < 4; j++) {
            const int col = n0 + wn + j * 8 + 2 * tig;
            float2 v0 = make_float2(acc[i][j][0], acc[i][j][1]);
            float2 v1 = make_float2(acc[i][j][2], acc[i][j][3]);
            if (HASBIAS) {
                const float b0 = bias[col], b1 = bias[col + 1];
                v0.x += b0; v0.y += b1;
                v1.x += b0; v1.y += b1;
            }
            *reinterpret_cast<float2*>(C + (size_t)r0 * N + col) = v0;
            *reinterpret_cast<float2*>(C + (size_t)(r0 + 8) * N + col) = v1;
        }
    }
}

// ---------------------------------------------------------------------------
// Transpose per batch: out[b][h][s] = in[b][s][h]
// ---------------------------------------------------------------------------
__global__ __launch_bounds__(256) void transpose_kernel(
    const float* __restrict__ in, float* __restrict__ out)
{
    __shared__ float tile[32][33];
    const int b = blockIdx.z;
    const int s0 = blockIdx.x * 32;
    const int h0 = blockIdx.y * 32;
    const float* ip = in + (size_t)b * SS * HH;
    float* op = out + (size_t)b * SS * HH;
    const int tx = threadIdx.x & 31;
    const int ty = threadIdx.x >> 5;
#pragma unroll
    for (int r = ty; r < 32; r += 8)
        tile[r][tx] = ip[(size_t)(s0 + r) * HH + h0 + tx];
    __syncthreads();
#pragma unroll
    for (int r = ty; r < 32; r += 8)
        op[(size_t)(h0 + r) * SS + s0 + tx] = tile[tx][r];
}

// ---------------------------------------------------------------------------
// Row softmax with scale + causal + key mask (matches reference semantics)
// ---------------------------------------------------------------------------
__global__ __launch_bounds__(256) void softmax_kernel(
    float* __restrict__ attn, const int* __restrict__ mask)
{
    const int row = blockIdx.x;
    const int b = row / SS;
    const int i = row % SS;
    float* p = attn + (size_t)b * SS * SS + (size_t)i * SS;
    const int* mrow = mask + (size_t)b * SS;
    const float scale = 0.03125f;

    __shared__ float red[256];
    const int tid = threadIdx.x;

    float mx = -FLT_MAX;
    for (int j = tid; j < SS; j += 256) {
        float v = (j <= i && mrow[j] != 0) ? p[j] * scale : -FLT_MAX;
        mx = fmaxf(mx, v);
    }
    red[tid] = mx; __syncthreads();
    for (int s = 128; s > 0; s >>= 1) {
        if (tid < s) red[tid] = fmaxf(red[tid], red[tid + s]);
        __syncthreads();
    }
    mx = red[0]; __syncthreads();

    float sum = 0.0f;
    for (int j = tid; j < SS; j += 256) {
        float v = (j <= i && mrow[j] != 0) ? p[j] * scale : -FLT_MAX;
        float e = __expf(v - mx);
        p[j] = e;
        sum += e;
    }
    red[tid] = sum; __syncthreads();
    for (int s = 128; s > 0; s >>= 1) {
        if (tid < s) red[tid] += red[tid + s];
        __syncthreads();
    }
    const float inv = 1.0f / red[0];
    for (int j = tid; j < SS; j += 256) p[j] *= inv;
}

// ---------------------------------------------------------------------------
extern "C" void kernel_launch(void* const* d_in, const int* in_sizes, int n_in,
                              void* d_out, int out_size)
{
    const float* x    = (const float*)d_in[0];
    const int*   mask = (const int*)  d_in[1];
    const float* Wq   = (const float*)d_in[2];
    const float* bq   = (const float*)d_in[3];
    const float* Wk   = (const float*)d_in[4];
    const float* bk   = (const float*)d_in[5];
    const float* Wv   = (const float*)d_in[6];
    const float* bv   = (const float*)d_in[7];
    const float* Wo   = (const float*)d_in[8];
    const float* bo   = (const float*)d_in[9];

    float *q, *k, *v, *vt, *po, *attn_scratch;
    cudaGetSymbolAddress((void**)&q,  g_q);
    cudaGetSymbolAddress((void**)&k,  g_k);
    cudaGetSymbolAddress((void**)&v,  g_v);
    cudaGetSymbolAddress((void**)&vt, g_vt);
    cudaGetSymbolAddress((void**)&po, g_po);
    cudaGetSymbolAddress((void**)&attn_scratch, g_attn);

    const long long OUT_N  = (long long)BB * SS * HH;
    const long long ATTN_N = (long long)BB * SS * SS;

    float* out_dst  = (float*)d_out;
    float* attn_dst = attn_scratch;
    if ((long long)out_size >= OUT_N + ATTN_N) {
        attn_dst = (float*)d_out + OUT_N;
    } else if ((long long)out_size == ATTN_N) {
        attn_dst = (float*)d_out;
        out_dst  = q;  // q dead after scores
    }

    const int M_TOK = BB * SS;  // 8192
    dim3 blk(256);

    // 1) QKV projections
    {
        dim3 grid(HH / 128, M_TOK / 128, 1);
        mma_gemm_nt<true><<<grid, blk>>>(x, Wq, bq, q, M_TOK, HH, HH, 0, 0, 0);
        mma_gemm_nt<true><<<grid, blk>>>(x, Wk, bk, k, M_TOK, HH, HH, 0, 0, 0);
        mma_gemm_nt<true><<<grid, blk>>>(x, Wv, bv, v, M_TOK, HH, HH, 0, 0, 0);
    }

    // 2) V^T (so PV is NT as well)
    {
        dim3 grid(SS / 32, HH / 32, BB);
        transpose_kernel<<<grid, blk>>>(v, vt);
    }

    // 3) scores = Q @ K^T per batch
    {
        dim3 grid(SS / 128, SS / 128, BB);
        mma_gemm_nt<false><<<grid, blk>>>(
            q, k, nullptr, attn_dst, SS, SS, HH,
            (long long)SS * HH, (long long)SS * HH, (long long)SS * SS);
    }

    // 4) softmax (scale + causal + key mask)
    softmax_kernel<<<BB * SS, 256>>>(attn_dst, mask);

    // 5) PV: attn @ V  (B operand = V^T as [H, S])
    {
        dim3 grid(HH / 128, SS / 128, BB);
        mma_gemm_nt<false><<<grid, blk>>>(
            attn_dst, vt, nullptr, po, SS, HH, SS,
            (long long)SS * SS, (long long)SS * HH, (long long)SS * HH);
    }

    // 6) output projection
    {
        dim3 grid(HH / 128, M_TOK / 128, 1);
        mma_gemm_nt<true><<<grid, blk>>>(po, Wo, bo, out_dst, M_TOK, HH, HH, 0, 0, 0);
    }
}

// round 5
// speedup vs baseline: 3.8724x; 1.0690x over previous
#include <cuda_runtime.h>
#include <cstdint>
#include <float.h>

#define BB 4
#define SS 2048
#define HH 1024

// ---------------- scratch (allocation-free) ----------------
__device__ float g_q [(size_t)BB * SS * HH];
__device__ float g_k [(size_t)BB * SS * HH];
__device__ float g_v [(size_t)BB * SS * HH];
__device__ float g_vt[(size_t)BB * SS * HH];
__device__ float g_po[(size_t)BB * SS * HH];
__device__ float g_attn[(size_t)BB * SS * SS];
__device__ float g_xr [(size_t)BB * SS * HH];     // tf32-rounded x
__device__ float g_wr [(size_t)4 * HH * HH];      // tf32-rounded Wq,Wk,Wv,Wo

__device__ __forceinline__ uint32_t smem_u32(const void* p) {
    uint32_t a;
    asm("{ .reg .u64 t; cvta.to.shared.u64 t, %1; cvt.u32.u64 %0, t; }" : "=r"(a) : "l"(p));
    return a;
}
__device__ __forceinline__ uint32_t f2tf32(float f) {
    uint32_t r;
    asm("cvt.rna.tf32.f32 %0, %1;" : "=r"(r) : "f"(f));
    return r;
}
__device__ __forceinline__ float rnd_tf32(float f) {
    return __uint_as_float(f2tf32(f));
}
__device__ __forceinline__ void cp_async16(uint32_t saddr, const void* gptr) {
    asm volatile("cp.async.cg.shared.global [%0], [%1], 16;"
                 :: "r"(saddr), "l"(gptr) : "memory");
}
#define CP_COMMIT() asm volatile("cp.async.commit_group;" ::: "memory")

__device__ __forceinline__ void mma_tf32(float& c0, float& c1, float& c2, float& c3,
                                         uint32_t a0, uint32_t a1, uint32_t a2, uint32_t a3,
                                         uint32_t b0, uint32_t b1) {
    asm volatile(
        "mma.sync.aligned.m16n8k8.row.col.f32.tf32.tf32.f32 "
        "{%0,%1,%2,%3}, {%4,%5,%6,%7}, {%8,%9}, {%0,%1,%2,%3};"
        : "+f"(c0), "+f"(c1), "+f"(c2), "+f"(c3)
        : "r"(a0), "r"(a1), "r"(a2), "r"(a3), "r"(b0), "r"(b1));
}

// ---------------------------------------------------------------------------
// Round-copy: out[i] = tf32(in[i]); element counts are multiples of 1024.
// ---------------------------------------------------------------------------
__global__ __launch_bounds__(256) void round_copy_kernel(
    const float* __restrict__ in, float* __restrict__ out, int n4)
{
    int i = blockIdx.x * 256 + threadIdx.x;
    if (i < n4) {
        float4 v = reinterpret_cast<const float4*>(in)[i];
        v.x = rnd_tf32(v.x); v.y = rnd_tf32(v.y);
        v.z = rnd_tf32(v.z); v.w = rnd_tf32(v.w);
        reinterpret_cast<float4*>(out)[i] = v;
    }
}

// ---------------------------------------------------------------------------
// NT tf32 tensor-core GEMM: C[M,N] = A[M,K] @ B^T (+bias)
//   A: [M,K] row-major, B: [N,K] row-major, both PRE-ROUNDED to tf32 values.
//   Batched via blockIdx.z. Tile 128x128x16, 8 warps (2x4), warp tile 64x32,
//   m16n8k8 MMAs, cp.async double buffer, padded smem (stride 20 floats).
//   CSKIP:    skip tiles with block-col > block-row (causal scores)
//   TRIK:     limit K to (blockIdx.y+1)*128 (triangular attn in PV)
//   ROUNDOUT: round output to tf32 values (feeds another GEMM as operand)
// Requires M%128==0, N%128==0, K%16==0.
// ---------------------------------------------------------------------------
#define LDSF 20  // floats per smem row (16 + 4 pad)

template <bool HASBIAS, bool CSKIP, bool TRIK, bool ROUNDOUT>
__global__ __launch_bounds__(256) void mma_gemm_nt(
    const float* __restrict__ A, const float* __restrict__ B,
    const float* __restrict__ bias, float* __restrict__ C,
    int M, int N, int K,
    long long strA, long long strB, long long strC)
{
    if (CSKIP && blockIdx.x > blockIdx.y) return;

    __shared__ float As[2][128 * LDSF];
    __shared__ float Bs[2][128 * LDSF];

    const int tid  = threadIdx.x;
    const int wid  = tid >> 5;
    const int lane = tid & 31;
    const int g    = lane >> 2;
    const int tig  = lane & 3;
    const int m0   = blockIdx.y * 128;
    const int n0   = blockIdx.x * 128;
    const int wm   = (wid >> 2) * 64;
    const int wn   = (wid & 3) * 32;

    A += (long long)blockIdx.z * strA;
    B += (long long)blockIdx.z * strB;
    C += (long long)blockIdx.z * strC;

    const int Kend = TRIK ? min(K, (int)(blockIdx.y + 1) * 128) : K;
    const int T = Kend >> 4;

    const uint32_t sAs = smem_u32(&As[0][0]);
    const uint32_t sBs = smem_u32(&Bs[0][0]);
    const int lrow0 = tid >> 2;
    const int lch0  = tid & 3;
    const int lrow1 = lrow0 + 64;

    float acc[4][4][4];
#pragma unroll
    for (int i = 0; i < 4; i++)
#pragma unroll
        for (int j = 0; j < 4; j++)
#pragma unroll
            for (int r = 0; r < 4; r++) acc[i][j][r] = 0.0f;

    // ---- prefetch tile 0 ----
    cp_async16(sAs + (uint32_t)(lrow0 * LDSF + lch0 * 4) * 4,
               A + (size_t)(m0 + lrow0) * K + lch0 * 4);
    cp_async16(sAs + (uint32_t)(lrow1 * LDSF + lch0 * 4) * 4,
               A + (size_t)(m0 + lrow1) * K + lch0 * 4);
    cp_async16(sBs + (uint32_t)(lrow0 * LDSF + lch0 * 4) * 4,
               B + (size_t)(n0 + lrow0) * K + lch0 * 4);
    cp_async16(sBs + (uint32_t)(lrow1 * LDSF + lch0 * 4) * 4,
               B + (size_t)(n0 + lrow1) * K + lch0 * 4);
    CP_COMMIT();

    for (int t = 0; t < T; t++) {
        const int buf = t & 1;
        if (t + 1 < T) {
            const int nb = (t + 1) & 1;
            const int k0 = (t + 1) << 4;
            const uint32_t sa = sAs + (uint32_t)nb * (128 * LDSF * 4);
            const uint32_t sb = sBs + (uint32_t)nb * (128 * LDSF * 4);
            cp_async16(sa + (uint32_t)(lrow0 * LDSF + lch0 * 4) * 4,
                       A + (size_t)(m0 + lrow0) * K + k0 + lch0 * 4);
            cp_async16(sa + (uint32_t)(lrow1 * LDSF + lch0 * 4) * 4,
                       A + (size_t)(m0 + lrow1) * K + k0 + lch0 * 4);
            cp_async16(sb + (uint32_t)(lrow0 * LDSF + lch0 * 4) * 4,
                       B + (size_t)(n0 + lrow0) * K + k0 + lch0 * 4);
            cp_async16(sb + (uint32_t)(lrow1 * LDSF + lch0 * 4) * 4,
                       B + (size_t)(n0 + lrow1) * K + k0 + lch0 * 4);
            CP_COMMIT();
            asm volatile("cp.async.wait_group 1;" ::: "memory");
        } else {
            asm volatile("cp.async.wait_group 0;" ::: "memory");
        }
        __syncthreads();

        const float* Ab = As[buf];
        const float* Bb = Bs[buf];
#pragma unroll
        for (int kk = 0; kk < 16; kk += 8) {
            uint32_t af[4][4], bf[4][2];
#pragma unroll
            for (int i = 0; i < 4; i++) {
                const int mr = wm + i * 16 + g;
                af[i][0] = __float_as_uint(Ab[mr * LDSF + kk + tig]);
                af[i][1] = __float_as_uint(Ab[(mr + 8) * LDSF + kk + tig]);
                af[i][2] = __float_as_uint(Ab[mr * LDSF + kk + tig + 4]);
                af[i][3] = __float_as_uint(Ab[(mr + 8) * LDSF + kk + tig + 4]);
            }
#pragma unroll
            for (int j = 0; j < 4; j++) {
                const int nr = wn + j * 8 + g;
                bf[j][0] = __float_as_uint(Bb[nr * LDSF + kk + tig]);
                bf[j][1] = __float_as_uint(Bb[nr * LDSF + kk + tig + 4]);
            }
#pragma unroll
            for (int i = 0; i < 4; i++)
#pragma unroll
                for (int j = 0; j < 4; j++)
                    mma_tf32(acc[i][j][0], acc[i][j][1], acc[i][j][2], acc[i][j][3],
                             af[i][0], af[i][1], af[i][2], af[i][3],
                             bf[j][0], bf[j][1]);
        }
        __syncthreads();
    }

    // ---- epilogue ----
#pragma unroll
    for (int i = 0; i < 4; i++) {
        const int r0 = m0 + wm + i * 16 + g;
#pragma unroll
        for (int j = 0; j < 4; j++) {
            const int col = n0 + wn + j * 8 + 2 * tig;
            float2 v0 = make_float2(acc[i][j][0], acc[i][j][1]);
            float2 v1 = make_float2(acc[i][j][2], acc[i][j][3]);
            if (HASBIAS) {
                const float b0 = bias[col], b1 = bias[col + 1];
                v0.x += b0; v0.y += b1;
                v1.x += b0; v1.y += b1;
            }
            if (ROUNDOUT) {
                v0.x = rnd_tf32(v0.x); v0.y = rnd_tf32(v0.y);
                v1.x = rnd_tf32(v1.x); v1.y = rnd_tf32(v1.y);
            }
            *reinterpret_cast<float2*>(C + (size_t)r0 * N + col) = v0;
            *reinterpret_cast<float2*>(C + (size_t)(r0 + 8) * N + col) = v1;
        }
    }
}

// ---------------------------------------------------------------------------
// Transpose per batch: out[b][h][s] = in[b][s][h]
// ---------------------------------------------------------------------------
__global__ __launch_bounds__(256) void transpose_kernel(
    const float* __restrict__ in, float* __restrict__ out)
{
    __shared__ float tile[32][33];
    const int b = blockIdx.z;
    const int s0 = blockIdx.x * 32;
    const int h0 = blockIdx.y * 32;
    const float* ip = in + (size_t)b * SS * HH;
    float* op = out + (size_t)b * SS * HH;
    const int tx = threadIdx.x & 31;
    const int ty = threadIdx.x >> 5;
#pragma unroll
    for (int r = ty; r < 32; r += 8)
        tile[r][tx] = ip[(size_t)(s0 + r) * HH + h0 + tx];
    __syncthreads();
#pragma unroll
    for (int r = ty; r < 32; r += 8)
        op[(size_t)(h0 + r) * SS + s0 + tx] = tile[tx][r];
}

// ---------------------------------------------------------------------------
// Row softmax with scale + causal + key mask. Final values tf32-rounded
// (attn feeds PV as a GEMM operand).
// ---------------------------------------------------------------------------
__global__ __launch_bounds__(256) void softmax_kernel(
    float* __restrict__ attn, const int* __restrict__ mask)
{
    const int row = blockIdx.x;
    const int b = row / SS;
    const int i = row % SS;
    float* p = attn + (size_t)b * SS * SS + (size_t)i * SS;
    const int* mrow = mask + (size_t)b * SS;
    const float scale = 0.03125f;

    __shared__ float red[256];
    const int tid = threadIdx.x;

    float mx = -FLT_MAX;
    for (int j = tid; j < SS; j += 256) {
        float v = (j <= i && mrow[j] != 0) ? p[j] * scale : -FLT_MAX;
        mx = fmaxf(mx, v);
    }
    red[tid] = mx; __syncthreads();
    for (int s = 128; s > 0; s >>= 1) {
        if (tid < s) red[tid] = fmaxf(red[tid], red[tid + s]);
        __syncthreads();
    }
    mx = red[0]; __syncthreads();

    float sum = 0.0f;
    for (int j = tid; j < SS; j += 256) {
        float v = (j <= i && mrow[j] != 0) ? p[j] * scale : -FLT_MAX;
        float e = __expf(v - mx);
        p[j] = e;
        sum += e;
    }
    red[tid] = sum; __syncthreads();
    for (int s = 128; s > 0; s >>= 1) {
        if (tid < s) red[tid] += red[tid + s];
        __syncthreads();
    }
    const float inv = 1.0f / red[0];
    for (int j = tid; j < SS; j += 256) p[j] = rnd_tf32(p[j] * inv);
}

// ---------------------------------------------------------------------------
extern "C" void kernel_launch(void* const* d_in, const int* in_sizes, int n_in,
                              void* d_out, int out_size)
{
    const float* x    = (const float*)d_in[0];
    const int*   mask = (const int*)  d_in[1];
    const float* Wq   = (const float*)d_in[2];
    const float* bq   = (const float*)d_in[3];
    const float* Wk   = (const float*)d_in[4];
    const float* bk   = (const float*)d_in[5];
    const float* Wv   = (const float*)d_in[6];
    const float* bv   = (const float*)d_in[7];
    const float* Wo   = (const float*)d_in[8];
    const float* bo   = (const float*)d_in[9];

    float *q, *k, *v, *vt, *po, *attn_scratch, *xr, *wr;
    cudaGetSymbolAddress((void**)&q,  g_q);
    cudaGetSymbolAddress((void**)&k,  g_k);
    cudaGetSymbolAddress((void**)&v,  g_v);
    cudaGetSymbolAddress((void**)&vt, g_vt);
    cudaGetSymbolAddress((void**)&po, g_po);
    cudaGetSymbolAddress((void**)&attn_scratch, g_attn);
    cudaGetSymbolAddress((void**)&xr, g_xr);
    cudaGetSymbolAddress((void**)&wr, g_wr);

    const long long OUT_N  = (long long)BB * SS * HH;
    const long long ATTN_N = (long long)BB * SS * SS;

    float* out_dst  = (float*)d_out;
    float* attn_dst = attn_scratch;
    if ((long long)out_size >= OUT_N + ATTN_N) {
        attn_dst = (float*)d_out + OUT_N;
    } else if ((long long)out_size == ATTN_N) {
        attn_dst = (float*)d_out;
        out_dst  = q;  // q dead after scores
    }

    const int M_TOK = BB * SS;  // 8192
    dim3 blk(256);

    float* Wqr = wr;
    float* Wkr = wr + (size_t)HH * HH;
    float* Wvr = wr + (size_t)2 * HH * HH;
    float* Wor = wr + (size_t)3 * HH * HH;

    // 0) round x and weights to tf32 values (operands for MMA, no in-loop cvt)
    {
        const int xn4 = (BB * SS * HH) / 4;
        const int wn4 = (HH * HH) / 4;
        round_copy_kernel<<<(xn4 + 255) / 256, blk>>>(x,  xr,  xn4);
        round_copy_kernel<<<(wn4 + 255) / 256, blk>>>(Wq, Wqr, wn4);
        round_copy_kernel<<<(wn4 + 255) / 256, blk>>>(Wk, Wkr, wn4);
        round_copy_kernel<<<(wn4 + 255) / 256, blk>>>(Wv, Wvr, wn4);
        round_copy_kernel<<<(wn4 + 255) / 256, blk>>>(Wo, Wor, wn4);
    }

    // 1) QKV projections (outputs rounded: they feed scores/PV)
    {
        dim3 grid(HH / 128, M_TOK / 128, 1);
        mma_gemm_nt<true, false, false, true><<<grid, blk>>>(xr, Wqr, bq, q, M_TOK, HH, HH, 0, 0, 0);
        mma_gemm_nt<true, false, false, true><<<grid, blk>>>(xr, Wkr, bk, k, M_TOK, HH, HH, 0, 0, 0);
        mma_gemm_nt<true, false, false, true><<<grid, blk>>>(xr, Wvr, bv, v, M_TOK, HH, HH, 0, 0, 0);
    }

    // 2) V^T (values already rounded)
    {
        dim3 grid(SS / 32, HH / 32, BB);
        transpose_kernel<<<grid, blk>>>(v, vt);
    }

    // 3) scores = Q @ K^T per batch, skipping fully-causal-masked tiles
    {
        dim3 grid(SS / 128, SS / 128, BB);
        mma_gemm_nt<false, true, false, false><<<grid, blk>>>(
            q, k, nullptr, attn_dst, SS, SS, HH,
            (long long)SS * HH, (long long)SS * HH, (long long)SS * SS);
    }

    // 4) softmax (scale + causal + key mask; writes 0 over masked region)
    softmax_kernel<<<BB * SS, 256>>>(attn_dst, mask);

    // 5) PV: attn @ V with triangular K limit (attn[i][j]=0 for j>i)
    {
        dim3 grid(HH / 128, SS / 128, BB);
        mma_gemm_nt<false, false, true, true><<<grid, blk>>>(
            attn_dst, vt, nullptr, po, SS, HH, SS,
            (long long)SS * SS, (long long)SS * HH, (long long)SS * HH);
    }

    // 6) output projection (final output: no rounding)
    {
        dim3 grid(HH / 128, M_TOK / 128, 1);
        mma_gemm_nt<true, false, false, false><<<grid, blk>>>(po, Wor, bo, out_dst, M_TOK, HH, HH, 0, 0, 0);
    }
}

// round 6
// speedup vs baseline: 6.9588x; 1.7970x over previous
#include <cuda_runtime.h>
#include <cuda_fp16.h>
#include <cstdint>
#include <float.h>

#define BB 4
#define SS 2048
#define HH 1024

// ---------------- scratch (allocation-free) ----------------
__device__ __half g_q [(size_t)BB * SS * HH];
__device__ __half g_k [(size_t)BB * SS * HH];
__device__ __half g_v [(size_t)BB * SS * HH];
__device__ __half g_vt[(size_t)BB * SS * HH];
__device__ __half g_po[(size_t)BB * SS * HH];
__device__ float  g_attn[(size_t)BB * SS * SS];    // fp32 scores/attn
__device__ __half g_attn16[(size_t)BB * SS * SS];  // fp16 attn (PV operand)
__device__ __half g_xh [(size_t)BB * SS * HH];     // fp16 x
__device__ __half g_wh [(size_t)4 * HH * HH];      // fp16 Wq,Wk,Wv,Wo

__device__ __forceinline__ uint32_t smem_u32(const void* p) {
    uint32_t a;
    asm("{ .reg .u64 t; cvta.to.shared.u64 t, %1; cvt.u32.u64 %0, t; }" : "=r"(a) : "l"(p));
    return a;
}
__device__ __forceinline__ void cp_async16(uint32_t saddr, const void* gptr) {
    asm volatile("cp.async.cg.shared.global [%0], [%1], 16;"
                 :: "r"(saddr), "l"(gptr) : "memory");
}
#define CP_COMMIT() asm volatile("cp.async.commit_group;" ::: "memory")

__device__ __forceinline__ void mma_f16(float& c0, float& c1, float& c2, float& c3,
                                        uint32_t a0, uint32_t a1, uint32_t a2, uint32_t a3,
                                        uint32_t b0, uint32_t b1) {
    asm volatile(
        "mma.sync.aligned.m16n8k16.row.col.f32.f16.f16.f32 "
        "{%0,%1,%2,%3}, {%4,%5,%6,%7}, {%8,%9}, {%0,%1,%2,%3};"
        : "+f"(c0), "+f"(c1), "+f"(c2), "+f"(c3)
        : "r"(a0), "r"(a1), "r"(a2), "r"(a3), "r"(b0), "r"(b1));
}

// ---------------------------------------------------------------------------
// half-convert copy: out[i] = fp16(in[i]); n4 = count/4
// ---------------------------------------------------------------------------
__global__ __launch_bounds__(256) void half_copy_kernel(
    const float* __restrict__ in, __half* __restrict__ out, int n4)
{
    int i = blockIdx.x * 256 + threadIdx.x;
    if (i < n4) {
        float4 v = reinterpret_cast<const float4*>(in)[i];
        __half2 lo = __floats2half2_rn(v.x, v.y);
        __half2 hi = __floats2half2_rn(v.z, v.w);
        uint2 pk;
        pk.x = *reinterpret_cast<uint32_t*>(&lo);
        pk.y = *reinterpret_cast<uint32_t*>(&hi);
        reinterpret_cast<uint2*>(out)[i] = pk;
    }
}

// ---------------------------------------------------------------------------
// NT fp16 tensor-core GEMM: C[M,N] = A[M,K] @ B^T (+bias, fp32)
//   A: [M,K], B: [N,K] row-major __half. Batched via blockIdx.z.
// Tile 128x128x32 (halves), 8 warps (2x4), warp tile 64x32, m16n8k16 MMAs,
// cp.async double buffer, padded smem (row stride 40 halves = 80B:
// fragment banks (20g + tig) % 32 all-distinct -> conflict-free).
//   CSKIP: skip tiles with block-col > block-row (causal scores)
//   TRIK : limit K to (blockIdx.y+1)*128 (triangular attn in PV)
// OutT: __half (feeds another GEMM) or float (final / scores).
// Requires M%128==0, N%128==0, K%32==0.
// ---------------------------------------------------------------------------
#define LDSH 40  // halves per smem row (32 + 8 pad), 80 bytes

template <typename OutT, bool HASBIAS, bool CSKIP, bool TRIK>
__global__ __launch_bounds__(256) void mma_gemm_nt(
    const __half* __restrict__ A, const __half* __restrict__ B,
    const float* __restrict__ bias, OutT* __restrict__ C,
    int M, int N, int K,
    long long strA, long long strB, long long strC)
{
    if (CSKIP && blockIdx.x > blockIdx.y) return;

    __shared__ __half As[2][128 * LDSH];
    __shared__ __half Bs[2][128 * LDSH];

    const int tid  = threadIdx.x;
    const int wid  = tid >> 5;
    const int lane = tid & 31;
    const int g    = lane >> 2;
    const int tig  = lane & 3;
    const int m0   = blockIdx.y * 128;
    const int n0   = blockIdx.x * 128;
    const int wm   = (wid >> 2) * 64;
    const int wn   = (wid & 3) * 32;

    A += (long long)blockIdx.z * strA;
    B += (long long)blockIdx.z * strB;
    C += (long long)blockIdx.z * strC;

    const int Kend = TRIK ? min(K, (int)(blockIdx.y + 1) * 128) : K;
    const int T = Kend >> 5;  // 32-half k-chunks

    const uint32_t sAs = smem_u32(&As[0][0]);
    const uint32_t sBs = smem_u32(&Bs[0][0]);
    // loader: tile = 128 rows x 4 chunks(16B). chunk c: row=c>>2, ch=c&3.
    const int lr0 = tid >> 2,  lc0 = tid & 3;          // c = tid
    const int lr1 = lr0 + 64;                          // c = tid + 256

    float acc[4][4][4];
#pragma unroll
    for (int i = 0; i < 4; i++)
#pragma unroll
        for (int j = 0; j < 4; j++)
#pragma unroll
            for (int r = 0; r < 4; r++) acc[i][j][r] = 0.0f;

    // ---- prefetch tile 0 ----
    cp_async16(sAs + (uint32_t)(lr0 * LDSH + lc0 * 8) * 2,
               A + (size_t)(m0 + lr0) * K + lc0 * 8);
    cp_async16(sAs + (uint32_t)(lr1 * LDSH + lc0 * 8) * 2,
               A + (size_t)(m0 + lr1) * K + lc0 * 8);
    cp_async16(sBs + (uint32_t)(lr0 * LDSH + lc0 * 8) * 2,
               B + (size_t)(n0 + lr0) * K + lc0 * 8);
    cp_async16(sBs + (uint32_t)(lr1 * LDSH + lc0 * 8) * 2,
               B + (size_t)(n0 + lr1) * K + lc0 * 8);
    CP_COMMIT();

    for (int t = 0; t < T; t++) {
        const int buf = t & 1;
        if (t + 1 < T) {
            const int nb = (t + 1) & 1;
            const int k0 = (t + 1) << 5;
            const uint32_t sa = sAs + (uint32_t)nb * (128 * LDSH * 2);
            const uint32_t sb = sBs + (uint32_t)nb * (128 * LDSH * 2);
            cp_async16(sa + (uint32_t)(lr0 * LDSH + lc0 * 8) * 2,
                       A + (size_t)(m0 + lr0) * K + k0 + lc0 * 8);
            cp_async16(sa + (uint32_t)(lr1 * LDSH + lc0 * 8) * 2,
                       A + (size_t)(m0 + lr1) * K + k0 + lc0 * 8);
            cp_async16(sb + (uint32_t)(lr0 * LDSH + lc0 * 8) * 2,
                       B + (size_t)(n0 + lr0) * K + k0 + lc0 * 8);
            cp_async16(sb + (uint32_t)(lr1 * LDSH + lc0 * 8) * 2,
                       B + (size_t)(n0 + lr1) * K + k0 + lc0 * 8);
            CP_COMMIT();
            asm volatile("cp.async.wait_group 1;" ::: "memory");
        } else {
            asm volatile("cp.async.wait_group 0;" ::: "memory");
        }
        __syncthreads();

        const __half* Ab = As[buf];
        const __half* Bb = Bs[buf];
#pragma unroll
        for (int kk = 0; kk < 32; kk += 16) {
            uint32_t af[4][4], bf[4][2];
#pragma unroll
            for (int i = 0; i < 4; i++) {
                const int mr = wm + i * 16 + g;
                af[i][0] = *reinterpret_cast<const uint32_t*>(&Ab[mr * LDSH + kk + 2 * tig]);
                af[i][1] = *reinterpret_cast<const uint32_t*>(&Ab[(mr + 8) * LDSH + kk + 2 * tig]);
                af[i][2] = *reinterpret_cast<const uint32_t*>(&Ab[mr * LDSH + kk + 8 + 2 * tig]);
                af[i][3] = *reinterpret_cast<const uint32_t*>(&Ab[(mr + 8) * LDSH + kk + 8 + 2 * tig]);
            }
#pragma unroll
            for (int j = 0; j < 4; j++) {
                const int nr = wn + j * 8 + g;
                bf[j][0] = *reinterpret_cast<const uint32_t*>(&Bb[nr * LDSH + kk + 2 * tig]);
                bf[j][1] = *reinterpret_cast<const uint32_t*>(&Bb[nr * LDSH + kk + 8 + 2 * tig]);
            }
#pragma unroll
            for (int i = 0; i < 4; i++)
#pragma unroll
                for (int j = 0; j < 4; j++)
                    mma_f16(acc[i][j][0], acc[i][j][1], acc[i][j][2], acc[i][j][3],
                            af[i][0], af[i][1], af[i][2], af[i][3],
                            bf[j][0], bf[j][1]);
        }
        __syncthreads();
    }

    // ---- epilogue ----
#pragma unroll
    for (int i = 0; i < 4; i++) {
        const int r0 = m0 + wm + i * 16 + g;
#pragma unroll
        for (int j = 0; j < 4; j++) {
            const int col = n0 + wn + j * 8 + 2 * tig;
            float v00 = acc[i][j][0], v01 = acc[i][j][1];
            float v10 = acc[i][j][2], v11 = acc[i][j][3];
            if (HASBIAS) {
                const float b0 = bias[col], b1 = bias[col + 1];
                v00 += b0; v01 += b1; v10 += b0; v11 += b1;
            }
            if (sizeof(OutT) == 2) {
                __half2 h0 = __floats2half2_rn(v00, v01);
                __half2 h1 = __floats2half2_rn(v10, v11);
                *reinterpret_cast<__half2*>((__half*)C + (size_t)r0 * N + col) = h0;
                *reinterpret_cast<__half2*>((__half*)C + (size_t)(r0 + 8) * N + col) = h1;
            } else {
                *reinterpret_cast<float2*>((float*)C + (size_t)r0 * N + col) =
                    make_float2(v00, v01);
                *reinterpret_cast<float2*>((float*)C + (size_t)(r0 + 8) * N + col) =
                    make_float2(v10, v11);
            }
        }
    }
}

// ---------------------------------------------------------------------------
// fp16 transpose per batch: out[b][h][s] = in[b][s][h]
// ---------------------------------------------------------------------------
__global__ __launch_bounds__(256) void transpose_kernel(
    const __half* __restrict__ in, __half* __restrict__ out)
{
    __shared__ __half tile[32][34];
    const int b = blockIdx.z;
    const int s0 = blockIdx.x * 32;
    const int h0 = blockIdx.y * 32;
    const __half* ip = in + (size_t)b * SS * HH;
    __half* op = out + (size_t)b * SS * HH;
    const int tx = threadIdx.x & 31;
    const int ty = threadIdx.x >> 5;
#pragma unroll
    for (int r = ty; r < 32; r += 8)
        tile[r][tx] = ip[(size_t)(s0 + r) * HH + h0 + tx];
    __syncthreads();
#pragma unroll
    for (int r = ty; r < 32; r += 8)
        op[(size_t)(h0 + r) * SS + s0 + tx] = tile[tx][r];
}

// ---------------------------------------------------------------------------
// Row softmax (fp32) with scale + causal + key mask. Writes fp32 attn
// (reference output) AND fp16 attn (PV GEMM operand).
// ---------------------------------------------------------------------------
__global__ __launch_bounds__(256) void softmax_kernel(
    float* __restrict__ attn, __half* __restrict__ attn16,
    const int* __restrict__ mask)
{
    const int row = blockIdx.x;
    const int b = row / SS;
    const int i = row % SS;
    float* p = attn + (size_t)b * SS * SS + (size_t)i * SS;
    __half* p16 = attn16 + (size_t)b * SS * SS + (size_t)i * SS;
    const int* mrow = mask + (size_t)b * SS;
    const float scale = 0.03125f;

    __shared__ float red[256];
    const int tid = threadIdx.x;

    float mx = -FLT_MAX;
    for (int j = tid; j < SS; j += 256) {
        float v = (j <= i && mrow[j] != 0) ? p[j] * scale : -FLT_MAX;
        mx = fmaxf(mx, v);
    }
    red[tid] = mx; __syncthreads();
    for (int s = 128; s > 0; s >>= 1) {
        if (tid < s) red[tid] = fmaxf(red[tid], red[tid + s]);
        __syncthreads();
    }
    mx = red[0]; __syncthreads();

    float sum = 0.0f;
    for (int j = tid; j < SS; j += 256) {
        float v = (j <= i && mrow[j] != 0) ? p[j] * scale : -FLT_MAX;
        float e = __expf(v - mx);
        p[j] = e;
        sum += e;
    }
    red[tid] = sum; __syncthreads();
    for (int s = 128; s > 0; s >>= 1) {
        if (tid < s) red[tid] += red[tid + s];
        __syncthreads();
    }
    const float inv = 1.0f / red[0];
    for (int j = tid; j < SS; j += 256) {
        float v = p[j] * inv;
        p[j] = v;
        p16[j] = __float2half_rn(v);
    }
}

// ---------------------------------------------------------------------------
extern "C" void kernel_launch(void* const* d_in, const int* in_sizes, int n_in,
                              void* d_out, int out_size)
{
    const float* x    = (const float*)d_in[0];
    const int*   mask = (const int*)  d_in[1];
    const float* Wq   = (const float*)d_in[2];
    const float* bq   = (const float*)d_in[3];
    const float* Wk   = (const float*)d_in[4];
    const float* bk   = (const float*)d_in[5];
    const float* Wv   = (const float*)d_in[6];
    const float* bv   = (const float*)d_in[7];
    const float* Wo   = (const float*)d_in[8];
    const float* bo   = (const float*)d_in[9];

    __half *q, *k, *v, *vt, *po, *attn16, *xh, *wh;
    float *attn_scratch;
    cudaGetSymbolAddress((void**)&q,  g_q);
    cudaGetSymbolAddress((void**)&k,  g_k);
    cudaGetSymbolAddress((void**)&v,  g_v);
    cudaGetSymbolAddress((void**)&vt, g_vt);
    cudaGetSymbolAddress((void**)&po, g_po);
    cudaGetSymbolAddress((void**)&attn_scratch, g_attn);
    cudaGetSymbolAddress((void**)&attn16, g_attn16);
    cudaGetSymbolAddress((void**)&xh, g_xh);
    cudaGetSymbolAddress((void**)&wh, g_wh);

    const long long OUT_N  = (long long)BB * SS * HH;
    const long long ATTN_N = (long long)BB * SS * SS;

    float* out_dst  = (float*)d_out;
    float* attn_dst = attn_scratch;
    if ((long long)out_size >= OUT_N + ATTN_N) {
        attn_dst = (float*)d_out + OUT_N;
    } else if ((long long)out_size == ATTN_N) {
        attn_dst = (float*)d_out;
        out_dst  = attn_scratch;  // unused sink (g_attn free in this branch)
    }

    const int M_TOK = BB * SS;  // 8192
    dim3 blk(256);

    __half* Wqh = wh;
    __half* Wkh = wh + (size_t)HH * HH;
    __half* Wvh = wh + (size_t)2 * HH * HH;
    __half* Woh = wh + (size_t)3 * HH * HH;

    // 0) convert x and weights to fp16 operands
    {
        const int xn4 = (BB * SS * HH) / 4;
        const int wn4 = (HH * HH) / 4;
        half_copy_kernel<<<(xn4 + 255) / 256, blk>>>(x,  xh,  xn4);
        half_copy_kernel<<<(wn4 + 255) / 256, blk>>>(Wq, Wqh, wn4);
        half_copy_kernel<<<(wn4 + 255) / 256, blk>>>(Wk, Wkh, wn4);
        half_copy_kernel<<<(wn4 + 255) / 256, blk>>>(Wv, Wvh, wn4);
        half_copy_kernel<<<(wn4 + 255) / 256, blk>>>(Wo, Woh, wn4);
    }

    // 1) QKV projections -> fp16 q/k/v
    {
        dim3 grid(HH / 128, M_TOK / 128, 1);
        mma_gemm_nt<__half, true, false, false><<<grid, blk>>>(xh, Wqh, bq, q, M_TOK, HH, HH, 0, 0, 0);
        mma_gemm_nt<__half, true, false, false><<<grid, blk>>>(xh, Wkh, bk, k, M_TOK, HH, HH, 0, 0, 0);
        mma_gemm_nt<__half, true, false, false><<<grid, blk>>>(xh, Wvh, bv, v, M_TOK, HH, HH, 0, 0, 0);
    }

    // 2) V^T (fp16) so PV is NT
    {
        dim3 grid(SS / 32, HH / 32, BB);
        transpose_kernel<<<grid, blk>>>(v, vt);
    }

    // 3) scores = Q @ K^T per batch (fp32 out), skipping causal-masked tiles
    {
        dim3 grid(SS / 128, SS / 128, BB);
        mma_gemm_nt<float, false, true, false><<<grid, blk>>>(
            q, k, nullptr, attn_dst, SS, SS, HH,
            (long long)SS * HH, (long long)SS * HH, (long long)SS * SS);
    }

    // 4) softmax (fp32 attn to output, fp16 attn for PV)
    softmax_kernel<<<BB * SS, 256>>>(attn_dst, attn16, mask);

    // 5) PV: attn16 @ V with triangular K limit -> fp16 po
    {
        dim3 grid(HH / 128, SS / 128, BB);
        mma_gemm_nt<__half, false, false, true><<<grid, blk>>>(
            attn16, vt, nullptr, po, SS, HH, SS,
            (long long)SS * SS, (long long)SS * HH, (long long)SS * HH);
    }

    // 6) output projection -> fp32 out + bias
    {
        dim3 grid(HH / 128, M_TOK / 128, 1);
        mma_gemm_nt<float, true, false, false><<<grid, blk>>>(po, Woh, bo, out_dst, M_TOK, HH, HH, 0, 0, 0);
    }
}